// round 3
// baseline (speedup 1.0000x reference)
#include <cuda_runtime.h>
#include <math.h>

#define BATCH 16
#define CHAN  768
#define NB    8
#define BS    96
#define NFFT  4096
#define NH    2048          // complex FFT size (real-packed)
#define MFREQ 2049          // N/2+1
#define MPAD  2052          // row stride (32B-aligned rows)
#define MT    64            // modes per GEMM CTA
#define LAMBDA 0.01f

// scratch: xf spectrum and post-MLP spectrum, layout [b][c][m], m-stride MPAD
__device__ float2 g_xf[(size_t)BATCH * CHAN * MPAD];
__device__ float2 g_o [(size_t)BATCH * CHAN * MPAD];

// ---------------------------------------------------------------------------
// Forward: real 4096-pt rfft via packed 2048-pt complex Stockham FFT.
// One CTA per row (b*CHAN + c), 256 threads, 40KB static smem.
// ---------------------------------------------------------------------------
__global__ void __launch_bounds__(256) fft_fwd_kernel(const float* __restrict__ x)
{
    __shared__ float2 sA[NH];
    __shared__ float2 sB[NH];
    __shared__ float2 tw[NH / 2];

    const int r = blockIdx.x;
    const int t = threadIdx.x;
    const float2* xrow = (const float2*)(x + (size_t)r * NFFT);

    // pack: z[j] = x[2j] + i x[2j+1]
    for (int j = t; j < NH; j += 256) sA[j] = xrow[j];
    // twiddle table: tw[p] = exp(-2*pi*i*p/NH)
    for (int p = t; p < NH / 2; p += 256) {
        float s, c;
        sincospif(-2.0f * (float)p / (float)NH, &s, &c);
        tw[p] = make_float2(c, s);
    }
    __syncthreads();

    // 11-stage radix-2 Stockham (natural in, natural out), DFT with e^{-}
    float2* src = sA;
    float2* dst = sB;
    for (int stage = 0; stage < 11; stage++) {
        const int s  = 1 << stage;
        const int mh = NH >> (stage + 1);
        for (int idx = t; idx < NH / 2; idx += 256) {
            const int p = idx >> stage;
            const int q = idx & (s - 1);
            float2 a = src[q + s * p];
            float2 b = src[q + s * (p + mh)];
            float2 sum = make_float2(a.x + b.x, a.y + b.y);
            float2 dif = make_float2(a.x - b.x, a.y - b.y);
            float2 w = tw[p << stage];
            float2 pd = make_float2(dif.x * w.x - dif.y * w.y,
                                    dif.x * w.y + dif.y * w.x);
            dst[q + s * (2 * p)]     = sum;
            dst[q + s * (2 * p + 1)] = pd;
        }
        __syncthreads();
        float2* tmp = src; src = dst; dst = tmp;
    }
    // result (natural order) is in src

    // unpack packed transform -> rfft bins, ortho scale 1/sqrt(4096) = 1/64
    float2* orow = &g_xf[(size_t)r * MPAD];
    for (int k = t; k <= NH; k += 256) {
        float2 zk = src[k & (NH - 1)];
        float2 zc = src[(NH - k) & (NH - 1)];
        // Xe = 0.5*(zk + conj(zc)), Xo = -0.5i*(zk - conj(zc))
        float xer = 0.5f * (zk.x + zc.x);
        float xei = 0.5f * (zk.y - zc.y);
        float dr  = zk.x - zc.x;
        float di  = zk.y + zc.y;
        float xor_ = 0.5f * di;
        float xoi  = -0.5f * dr;
        float s, c;
        sincospif(-(float)k / (float)NH, &s, &c);  // exp(-2*pi*i*k/NFFT)
        float Xr = xer + c * xor_ - s * xoi;
        float Xi = xei + c * xoi + s * xor_;
        orow[k] = make_float2(Xr * 0.015625f, Xi * 0.015625f);
    }
}

// ---------------------------------------------------------------------------
// Middle: per-block complex MLP over all (b, m).
//   h = crelu(xf @ W1 + b1);  o = softshrink(h @ W2 + b2)
// CTA = (m-tile, batch, block). Weight matrix staged in smem (73.7KB),
// X tile 96 x MT complex (48KB). Thread computes 6(o) x 4(m) complex tile.
// ---------------------------------------------------------------------------
__global__ void __launch_bounds__(256) mlp_kernel(
    const float* __restrict__ w1re, const float* __restrict__ w1im,
    const float* __restrict__ w2re, const float* __restrict__ w2im,
    const float* __restrict__ b1re, const float* __restrict__ b1im,
    const float* __restrict__ b2re, const float* __restrict__ b2im)
{
    extern __shared__ float2 sh[];
    float2* Ws = sh;              // [96][96]
    float2* Xs = sh + BS * BS;    // [96][MT]

    const int mt = blockIdx.x;
    const int b  = blockIdx.y;
    const int nb = blockIdx.z;
    const int m0 = mt * MT;
    const int tid = threadIdx.x;

    // stage W1
    {
        const float* wre = w1re + nb * BS * BS;
        const float* wim = w1im + nb * BS * BS;
        for (int i = tid; i < BS * BS; i += 256)
            Ws[i] = make_float2(__ldg(wre + i), __ldg(wim + i));
    }
    // stage X tile
    for (int idx = tid; idx < BS * MT; idx += 256) {
        const int i  = idx / MT;
        const int mm = idx - i * MT;
        const int m  = m0 + mm;
        Xs[idx] = (m < MFREQ)
            ? g_xf[(size_t)(b * CHAN + nb * BS + i) * MPAD + m]
            : make_float2(0.f, 0.f);
    }
    __syncthreads();

    const int tx = tid & 15;    // m group
    const int ty = tid >> 4;    // o group
    const int ob = ty * 6;
    const int mb = tx * 4;

    float ar[6][4], ai[6][4];
#pragma unroll
    for (int o = 0; o < 6; o++)
#pragma unroll
        for (int u = 0; u < 4; u++) { ar[o][u] = 0.f; ai[o][u] = 0.f; }

    // layer 1
    for (int i = 0; i < BS; i++) {
        float2 xv[4];
#pragma unroll
        for (int u = 0; u < 4; u++) xv[u] = Xs[i * MT + mb + u];
#pragma unroll
        for (int o = 0; o < 6; o++) {
            float2 w = Ws[i * BS + ob + o];
#pragma unroll
            for (int u = 0; u < 4; u++) {
                ar[o][u] += xv[u].x * w.x - xv[u].y * w.y;
                ai[o][u] += xv[u].x * w.y + xv[u].y * w.x;
            }
        }
    }

    // bias + crelu
    {
        const float* B1r = b1re + nb * BS;
        const float* B1i = b1im + nb * BS;
#pragma unroll
        for (int o = 0; o < 6; o++) {
            float br = __ldg(B1r + ob + o), bi = __ldg(B1i + ob + o);
#pragma unroll
            for (int u = 0; u < 4; u++) {
                ar[o][u] = fmaxf(ar[o][u] + br, 0.f);
                ai[o][u] = fmaxf(ai[o][u] + bi, 0.f);
            }
        }
    }

    __syncthreads();   // everyone done reading Xs/Ws

    // write H into Xs; stage W2 into Ws
#pragma unroll
    for (int o = 0; o < 6; o++)
#pragma unroll
        for (int u = 0; u < 4; u++)
            Xs[(ob + o) * MT + mb + u] = make_float2(ar[o][u], ai[o][u]);
    {
        const float* wre = w2re + nb * BS * BS;
        const float* wim = w2im + nb * BS * BS;
        for (int i = tid; i < BS * BS; i += 256)
            Ws[i] = make_float2(__ldg(wre + i), __ldg(wim + i));
    }
    __syncthreads();

#pragma unroll
    for (int o = 0; o < 6; o++)
#pragma unroll
        for (int u = 0; u < 4; u++) { ar[o][u] = 0.f; ai[o][u] = 0.f; }

    // layer 2
    for (int i = 0; i < BS; i++) {
        float2 xv[4];
#pragma unroll
        for (int u = 0; u < 4; u++) xv[u] = Xs[i * MT + mb + u];
#pragma unroll
        for (int o = 0; o < 6; o++) {
            float2 w = Ws[i * BS + ob + o];
#pragma unroll
            for (int u = 0; u < 4; u++) {
                ar[o][u] += xv[u].x * w.x - xv[u].y * w.y;
                ai[o][u] += xv[u].x * w.y + xv[u].y * w.x;
            }
        }
    }

    // bias + softshrink + store
    {
        const float* B2r = b2re + nb * BS;
        const float* B2i = b2im + nb * BS;
#pragma unroll
        for (int o = 0; o < 6; o++) {
            float br = __ldg(B2r + ob + o), bi = __ldg(B2i + ob + o);
            float2* grow = &g_o[(size_t)(b * CHAN + nb * BS + ob + o) * MPAD];
#pragma unroll
            for (int u = 0; u < 4; u++) {
                const int m = m0 + mb + u;
                if (m < MFREQ) {
                    float vr = ar[o][u] + br;
                    float vi = ai[o][u] + bi;
                    float tr = fabsf(vr) - LAMBDA;
                    float ti = fabsf(vi) - LAMBDA;
                    vr = (tr > 0.f) ? copysignf(tr, vr) : 0.f;
                    vi = (ti > 0.f) ? copysignf(ti, vi) : 0.f;
                    grow[m] = make_float2(vr, vi);
                }
            }
        }
    }
}

// ---------------------------------------------------------------------------
// Inverse: irfft(4096, ortho) via packed 2048-pt inverse Stockham, + bias x.
// Imag parts of bins 0 and N/2 are ignored (pocketfft c2r semantics).
// ---------------------------------------------------------------------------
__global__ void __launch_bounds__(256) fft_inv_kernel(const float* __restrict__ x,
                                                      float* __restrict__ y)
{
    __shared__ float2 sA[NH];
    __shared__ float2 sB[NH];
    __shared__ float2 tw[NH / 2];

    const int r = blockIdx.x;
    const int t = threadIdx.x;
    const float2* orow = &g_o[(size_t)r * MPAD];

    // twiddles for inverse: tw[p] = exp(+2*pi*i*p/NH)
    for (int p = t; p < NH / 2; p += 256) {
        float s, c;
        sincospif(2.0f * (float)p / (float)NH, &s, &c);
        tw[p] = make_float2(c, s);
    }

    // build packed spectrum Z[k] = Xe[k] + i*Xo[k]
    for (int k = t; k < NH; k += 256) {
        float2 a  = orow[k];
        float2 bb = orow[NH - k];       // k=0 -> bin 2048
        if (k == 0) { a.y = 0.f; bb.y = 0.f; }   // c2r ignores these imags
        float xer = 0.5f * (a.x + bb.x);
        float xei = 0.5f * (a.y - bb.y);
        float dr  = 0.5f * (a.x - bb.x);
        float di  = 0.5f * (a.y + bb.y);
        float s, c;
        sincospif((float)k / (float)NH, &s, &c);  // exp(+2*pi*i*k/NFFT)
        float xor_ = c * dr - s * di;
        float xoi  = c * di + s * dr;
        sA[k] = make_float2(xer - xoi, xei + xor_);
    }
    __syncthreads();

    // 11-stage inverse Stockham (conjugated twiddles -> unnormalized IDFT sum)
    float2* src = sA;
    float2* dst = sB;
    for (int stage = 0; stage < 11; stage++) {
        const int s  = 1 << stage;
        const int mh = NH >> (stage + 1);
        for (int idx = t; idx < NH / 2; idx += 256) {
            const int p = idx >> stage;
            const int q = idx & (s - 1);
            float2 a = src[q + s * p];
            float2 b = src[q + s * (p + mh)];
            float2 sum = make_float2(a.x + b.x, a.y + b.y);
            float2 dif = make_float2(a.x - b.x, a.y - b.y);
            float2 w = tw[p << stage];
            float2 pd = make_float2(dif.x * w.x - dif.y * w.y,
                                    dif.x * w.y + dif.y * w.x);
            dst[q + s * (2 * p)]     = sum;
            dst[q + s * (2 * p + 1)] = pd;
        }
        __syncthreads();
        float2* tmp = src; src = dst; dst = tmp;
    }

    // unpack pairs, scale by sqrt(N)/NH = 1/32, add residual x
    const float2* xrow = (const float2*)(x + (size_t)r * NFFT);
    float2* yrow = (float2*)(y + (size_t)r * NFFT);
    for (int j = t; j < NH; j += 256) {
        float2 z  = src[j];
        float2 xp = xrow[j];
        yrow[j] = make_float2(z.x * 0.03125f + xp.x,
                              z.y * 0.03125f + xp.y);
    }
}

// ---------------------------------------------------------------------------
extern "C" void kernel_launch(void* const* d_in, const int* in_sizes, int n_in,
                              void* d_out, int out_size)
{
    const float* x    = (const float*)d_in[0];
    const float* w1re = (const float*)d_in[1];
    const float* w1im = (const float*)d_in[2];
    const float* w2re = (const float*)d_in[3];
    const float* w2im = (const float*)d_in[4];
    const float* b1re = (const float*)d_in[5];
    const float* b1im = (const float*)d_in[6];
    const float* b2re = (const float*)d_in[7];
    const float* b2im = (const float*)d_in[8];
    float* y = (float*)d_out;

    static int smem_set = 0;
    if (!smem_set) {
        // First call is the harness's non-captured correctness call, so the
        // attribute is set outside graph capture.
        cudaFuncSetAttribute(mlp_kernel,
                             cudaFuncAttributeMaxDynamicSharedMemorySize,
                             (BS * BS + BS * MT) * (int)sizeof(float2));
        smem_set = 1;
    }

    fft_fwd_kernel<<<BATCH * CHAN, 256>>>(x);

    dim3 grid((MFREQ + MT - 1) / MT, BATCH, NB);   // 33 x 16 x 8
    mlp_kernel<<<grid, 256, (BS * BS + BS * MT) * (int)sizeof(float2)>>>(
        w1re, w1im, w2re, w2im, b1re, b1im, b2re, b2im);

    fft_inv_kernel<<<BATCH * CHAN, 256>>>(x, y);
}

// round 6
// speedup vs baseline: 2.4129x; 2.4129x over previous
#include <cuda_runtime.h>
#include <math.h>
#include <stdint.h>

#define BATCH 16
#define CHAN  768
#define NB    8
#define BS    96
#define NFFT  4096
#define NH    2048          // complex FFT size (real-packed)
#define MFREQ 2049          // N/2+1
#define MPAD  2052          // row stride of spectrum scratch
#define LAMBDA 0.01f

// MLP tensor-core tiling
#define MT    128           // modes per CTA
#define XSTR  136           // X plane stride (conflict-free B frags)
#define WSTR  100           // W plane stride (conflict-free A frags)
#define KT    12            // 96 / 8

// scratch: xf spectrum and post-MLP spectrum, layout [b][c][m], m-stride MPAD
__device__ float2 g_xf[(size_t)BATCH * CHAN * MPAD];
__device__ float2 g_o [(size_t)BATCH * CHAN * MPAD];

__device__ __forceinline__ float2 cmul(float2 a, float2 b)
{
    return make_float2(a.x * b.x - a.y * b.y, a.x * b.y + a.y * b.x);
}

// ---------------------------------------------------------------------------
// Forward: real 4096-pt rfft via packed 2048-pt complex FFT.
// Stockham DIF: one radix-2 stage (s=1) + five radix-4 stages (s=2..512).
// ---------------------------------------------------------------------------
__global__ void __launch_bounds__(256) fft_fwd_kernel(const float* __restrict__ x)
{
    __shared__ float2 sA[NH];
    __shared__ float2 sB[NH];
    __shared__ float2 tw[NH / 2];

    const int r = blockIdx.x;
    const int t = threadIdx.x;
    const float2* xrow = (const float2*)(x + (size_t)r * NFFT);

    for (int j = t; j < NH; j += 256) sA[j] = xrow[j];
    for (int p = t; p < NH / 2; p += 256) {
        float s, c;
        sincospif(-2.0f * (float)p / (float)NH, &s, &c);
        tw[p] = make_float2(c, s);
    }
    __syncthreads();

    float2* src = sA;
    float2* dst = sB;

    // stage 0: radix-2, s=1
    for (int p = t; p < NH / 2; p += 256) {
        float2 a = src[p];
        float2 b = src[p + NH / 2];
        float2 sum = make_float2(a.x + b.x, a.y + b.y);
        float2 dif = make_float2(a.x - b.x, a.y - b.y);
        dst[2 * p]     = sum;
        dst[2 * p + 1] = cmul(dif, tw[p]);
    }
    __syncthreads();
    { float2* tmp = src; src = dst; dst = tmp; }

    // radix-4 stages: s = 2, 8, 32, 128, 512
#pragma unroll
    for (int sh = 1; sh <= 9; sh += 2) {
        const int s = 1 << sh;
        for (int idx = t; idx < NH / 4; idx += 256) {
            const int p = idx >> sh;
            const int q = idx & (s - 1);
            float2 a0 = src[idx];              // q + s*p
            float2 a1 = src[idx + 512];        // + s*mq, s*mq = NH/4
            float2 a2 = src[idx + 1024];
            float2 a3 = src[idx + 1536];
            float2 t0 = make_float2(a0.x + a2.x, a0.y + a2.y);
            float2 t1 = make_float2(a0.x - a2.x, a0.y - a2.y);
            float2 t2 = make_float2(a1.x + a3.x, a1.y + a3.y);
            float2 t3 = make_float2(a1.x - a3.x, a1.y - a3.y);
            float2 B0 = make_float2(t0.x + t2.x, t0.y + t2.y);
            float2 B2 = make_float2(t0.x - t2.x, t0.y - t2.y);
            // forward: B1 = t1 - i*t3, B3 = t1 + i*t3
            float2 B1 = make_float2(t1.x + t3.y, t1.y - t3.x);
            float2 B3 = make_float2(t1.x - t3.y, t1.y + t3.x);
            float2 w1 = tw[idx & ~(s - 1)];    // exp(-2pi*i * p*s / NH)
            float2 w2 = make_float2(w1.x * w1.x - w1.y * w1.y, 2.f * w1.x * w1.y);
            float2 w3 = cmul(w2, w1);
            const int ob = q + (p << (sh + 2));
            dst[ob]         = B0;
            dst[ob + s]     = cmul(B1, w1);
            dst[ob + 2 * s] = cmul(B2, w2);
            dst[ob + 3 * s] = cmul(B3, w3);
        }
        __syncthreads();
        float2* tmp = src; src = dst; dst = tmp;
    }

    // unpack packed transform -> rfft bins, ortho scale 1/64
    float2* orow = &g_xf[(size_t)r * MPAD];
    for (int k = t; k <= NH; k += 256) {
        float2 zk = src[k & (NH - 1)];
        float2 zc = src[(NH - k) & (NH - 1)];
        float xer = 0.5f * (zk.x + zc.x);
        float xei = 0.5f * (zk.y - zc.y);
        float dr  = zk.x - zc.x;
        float di  = zk.y + zc.y;
        float xor_ = 0.5f * di;
        float xoi  = -0.5f * dr;
        float s, c;
        sincospif(-(float)k / (float)NH, &s, &c);
        float Xr = xer + c * xor_ - s * xoi;
        float Xi = xei + c * xoi + s * xor_;
        orow[k] = make_float2(Xr * 0.015625f, Xi * 0.015625f);
    }
}

// ---------------------------------------------------------------------------
// tf32 helpers
// ---------------------------------------------------------------------------
__device__ __forceinline__ uint32_t f2tf32(float f)
{
    uint32_t r;
    asm("cvt.rna.tf32.f32 %0, %1;" : "=r"(r) : "f"(f));
    return r;
}

#define MMA_TF32(D, A, B)                                                   \
    asm volatile("mma.sync.aligned.m16n8k8.row.col.f32.tf32.tf32.f32 "      \
                 "{%0,%1,%2,%3}, {%4,%5,%6,%7}, {%8,%9}, {%0,%1,%2,%3};"    \
                 : "+f"((D)[0]), "+f"((D)[1]), "+f"((D)[2]), "+f"((D)[3])   \
                 : "r"((A)[0]), "r"((A)[1]), "r"((A)[2]), "r"((A)[3]),      \
                   "r"((B)[0]), "r"((B)[1]))

// complex GEMM over K=96: D[o][m] = sum_i W[i][o] * X[i][m]
// Wt planes [96][WSTR] (tf32 bits), X planes [96][XSTR] (tf32 bits).
__device__ __forceinline__ void cgemm96(
    const uint32_t* __restrict__ uWre, const uint32_t* __restrict__ uWim,
    const uint32_t* __restrict__ uXre, const uint32_t* __restrict__ uXim,
    int wo, int wm, int lane,
    float dre[3][4][4], float dim_[3][4][4])
{
    const int arow = lane >> 2, acol = lane & 3;
    const int brow = lane & 3,  bcol = lane >> 2;

    for (int kt = 0; kt < KT; kt++) {
        const int k0 = kt * 8;
        uint32_t are[3][4], aim[3][4], ain[3][4];
#pragma unroll
        for (int ti = 0; ti < 3; ti++) {
            const int base = (wo * 48 + ti * 16 + arow) * WSTR + k0 + acol;
            are[ti][0] = uWre[base];
            are[ti][1] = uWre[base + 8 * WSTR];
            are[ti][2] = uWre[base + 4];
            are[ti][3] = uWre[base + 8 * WSTR + 4];
            aim[ti][0] = uWim[base];
            aim[ti][1] = uWim[base + 8 * WSTR];
            aim[ti][2] = uWim[base + 4];
            aim[ti][3] = uWim[base + 8 * WSTR + 4];
#pragma unroll
            for (int u = 0; u < 4; u++) ain[ti][u] = aim[ti][u] ^ 0x80000000u;
        }
        uint32_t bre[4][2], bim[4][2];
#pragma unroll
        for (int tj = 0; tj < 4; tj++) {
            const int base = (k0 + brow) * XSTR + wm * 32 + tj * 8 + bcol;
            bre[tj][0] = uXre[base];
            bre[tj][1] = uXre[base + 4 * XSTR];
            bim[tj][0] = uXim[base];
            bim[tj][1] = uXim[base + 4 * XSTR];
        }
#pragma unroll
        for (int ti = 0; ti < 3; ti++)
#pragma unroll
            for (int tj = 0; tj < 4; tj++) {
                MMA_TF32(dre[ti][tj], are[ti], bre[tj]);
                MMA_TF32(dre[ti][tj], ain[ti], bim[tj]);
                MMA_TF32(dim_[ti][tj], are[ti], bim[tj]);
                MMA_TF32(dim_[ti][tj], aim[ti], bre[tj]);
            }
    }
}

// ---------------------------------------------------------------------------
// MLP via tf32 tensor cores. CTA=(m-tile 128, batch, block), 256 threads.
// ---------------------------------------------------------------------------
__global__ void __launch_bounds__(256) mlp_kernel(
    const float* __restrict__ w1re, const float* __restrict__ w1im,
    const float* __restrict__ w2re, const float* __restrict__ w2im,
    const float* __restrict__ b1re, const float* __restrict__ b1im,
    const float* __restrict__ b2re, const float* __restrict__ b2im)
{
    extern __shared__ float smem[];
    float* sWre = smem;                       // [96][WSTR]
    float* sWim = sWre + BS * WSTR;
    float* sXre = sWim + BS * WSTR;           // [96][XSTR]
    float* sXim = sXre + BS * XSTR;
    uint32_t* uWre = (uint32_t*)sWre;
    uint32_t* uWim = (uint32_t*)sWim;
    uint32_t* uXre = (uint32_t*)sXre;
    uint32_t* uXim = (uint32_t*)sXim;

    const int mt = blockIdx.x;
    const int b  = blockIdx.y;
    const int nb = blockIdx.z;
    const int m0 = mt * MT;
    const int tid  = threadIdx.x;
    const int lane = tid & 31;
    const int wid  = tid >> 5;
    const int wo = wid & 1;       // o half (0/1) -> 48 rows
    const int wm = wid >> 1;      // m quarter  -> 32 cols

    // stage W1 (transposed) + X tile, tf32-converted
    {
        const float* wre = w1re + nb * BS * BS;
        const float* wim = w1im + nb * BS * BS;
        for (int idx = tid; idx < BS * BS; idx += 256) {
            const int i = idx / BS, o = idx - i * BS;
            uWre[o * WSTR + i] = f2tf32(__ldg(wre + idx));
            uWim[o * WSTR + i] = f2tf32(__ldg(wim + idx));
        }
    }
    for (int idx = tid; idx < BS * MT; idx += 256) {
        const int i  = idx / MT;
        const int mm = idx - i * MT;
        const int m  = m0 + mm;
        float2 v = (m < MFREQ)
            ? g_xf[(size_t)(b * CHAN + nb * BS + i) * MPAD + m]
            : make_float2(0.f, 0.f);
        uXre[i * XSTR + mm] = f2tf32(v.x);
        uXim[i * XSTR + mm] = f2tf32(v.y);
    }
    __syncthreads();

    float dre[3][4][4], dim_[3][4][4];
#pragma unroll
    for (int ti = 0; ti < 3; ti++)
#pragma unroll
        for (int tj = 0; tj < 4; tj++)
#pragma unroll
            for (int u = 0; u < 4; u++) { dre[ti][tj][u] = 0.f; dim_[ti][tj][u] = 0.f; }

    // layer 1
    cgemm96(uWre, uWim, uXre, uXim, wo, wm, lane, dre, dim_);

    __syncthreads();   // all warps done reading W1/X planes

    // bias + crelu, H -> X planes (tf32); stage W2
    {
        const int crow  = lane >> 2;
        const int ccol0 = 2 * (lane & 3);
#pragma unroll
        for (int ti = 0; ti < 3; ti++) {
            const int oA = wo * 48 + ti * 16 + crow;
            const int oB = oA + 8;
            const float brA = __ldg(b1re + nb * BS + oA);
            const float biA = __ldg(b1im + nb * BS + oA);
            const float brB = __ldg(b1re + nb * BS + oB);
            const float biB = __ldg(b1im + nb * BS + oB);
#pragma unroll
            for (int tj = 0; tj < 4; tj++) {
                const int mA = wm * 32 + tj * 8 + ccol0;
                uXre[oA * XSTR + mA]     = f2tf32(fmaxf(dre[ti][tj][0] + brA, 0.f));
                uXre[oA * XSTR + mA + 1] = f2tf32(fmaxf(dre[ti][tj][1] + brA, 0.f));
                uXre[oB * XSTR + mA]     = f2tf32(fmaxf(dre[ti][tj][2] + brB, 0.f));
                uXre[oB * XSTR + mA + 1] = f2tf32(fmaxf(dre[ti][tj][3] + brB, 0.f));
                uXim[oA * XSTR + mA]     = f2tf32(fmaxf(dim_[ti][tj][0] + biA, 0.f));
                uXim[oA * XSTR + mA + 1] = f2tf32(fmaxf(dim_[ti][tj][1] + biA, 0.f));
                uXim[oB * XSTR + mA]     = f2tf32(fmaxf(dim_[ti][tj][2] + biB, 0.f));
                uXim[oB * XSTR + mA + 1] = f2tf32(fmaxf(dim_[ti][tj][3] + biB, 0.f));
            }
        }
        const float* wre = w2re + nb * BS * BS;
        const float* wim = w2im + nb * BS * BS;
        for (int idx = tid; idx < BS * BS; idx += 256) {
            const int i = idx / BS, o = idx - i * BS;
            uWre[o * WSTR + i] = f2tf32(__ldg(wre + idx));
            uWim[o * WSTR + i] = f2tf32(__ldg(wim + idx));
        }
    }
    __syncthreads();

#pragma unroll
    for (int ti = 0; ti < 3; ti++)
#pragma unroll
        for (int tj = 0; tj < 4; tj++)
#pragma unroll
            for (int u = 0; u < 4; u++) { dre[ti][tj][u] = 0.f; dim_[ti][tj][u] = 0.f; }

    // layer 2
    cgemm96(uWre, uWim, uXre, uXim, wo, wm, lane, dre, dim_);

    // bias + softshrink + store
    {
        const int crow  = lane >> 2;
        const int ccol0 = 2 * (lane & 3);
#pragma unroll
        for (int ti = 0; ti < 3; ti++) {
            const int oA = wo * 48 + ti * 16 + crow;
            const int oB = oA + 8;
            const float brA = __ldg(b2re + nb * BS + oA);
            const float biA = __ldg(b2im + nb * BS + oA);
            const float brB = __ldg(b2re + nb * BS + oB);
            const float biB = __ldg(b2im + nb * BS + oB);
            float2* rowA = &g_o[(size_t)(b * CHAN + nb * BS + oA) * MPAD];
            float2* rowB = &g_o[(size_t)(b * CHAN + nb * BS + oB) * MPAD];
#pragma unroll
            for (int tj = 0; tj < 4; tj++) {
#pragma unroll
                for (int e = 0; e < 2; e++) {
                    const int m = m0 + wm * 32 + tj * 8 + ccol0 + e;
                    if (m < MFREQ) {
                        {
                            float vr = dre[ti][tj][e] + brA;
                            float vi = dim_[ti][tj][e] + biA;
                            float tr = fabsf(vr) - LAMBDA;
                            float ti2 = fabsf(vi) - LAMBDA;
                            vr = (tr  > 0.f) ? copysignf(tr,  vr) : 0.f;
                            vi = (ti2 > 0.f) ? copysignf(ti2, vi) : 0.f;
                            rowA[m] = make_float2(vr, vi);
                        }
                        {
                            float vr = dre[ti][tj][e + 2] + brB;
                            float vi = dim_[ti][tj][e + 2] + biB;
                            float tr = fabsf(vr) - LAMBDA;
                            float ti2 = fabsf(vi) - LAMBDA;
                            vr = (tr  > 0.f) ? copysignf(tr,  vr) : 0.f;
                            vi = (ti2 > 0.f) ? copysignf(ti2, vi) : 0.f;
                            rowB[m] = make_float2(vr, vi);
                        }
                    }
                }
            }
        }
    }
}

// ---------------------------------------------------------------------------
// Inverse: irfft(4096, ortho) + residual x.  Same radix-(2,4^5) Stockham with
// conjugated butterflies; c2r ignores imag of bins 0 and N/2.
// ---------------------------------------------------------------------------
__global__ void __launch_bounds__(256) fft_inv_kernel(const float* __restrict__ x,
                                                      float* __restrict__ y)
{
    __shared__ float2 sA[NH];
    __shared__ float2 sB[NH];
    __shared__ float2 tw[NH / 2];

    const int r = blockIdx.x;
    const int t = threadIdx.x;
    const float2* orow = &g_o[(size_t)r * MPAD];

    for (int p = t; p < NH / 2; p += 256) {
        float s, c;
        sincospif(2.0f * (float)p / (float)NH, &s, &c);
        tw[p] = make_float2(c, s);
    }

    for (int k = t; k < NH; k += 256) {
        float2 a  = orow[k];
        float2 bb = orow[NH - k];
        if (k == 0) { a.y = 0.f; bb.y = 0.f; }
        float xer = 0.5f * (a.x + bb.x);
        float xei = 0.5f * (a.y - bb.y);
        float dr  = 0.5f * (a.x - bb.x);
        float di  = 0.5f * (a.y + bb.y);
        float s, c;
        sincospif((float)k / (float)NH, &s, &c);
        float xor_ = c * dr - s * di;
        float xoi  = c * di + s * dr;
        sA[k] = make_float2(xer - xoi, xei + xor_);
    }
    __syncthreads();

    float2* src = sA;
    float2* dst = sB;

    // stage 0: radix-2, s=1
    for (int p = t; p < NH / 2; p += 256) {
        float2 a = src[p];
        float2 b = src[p + NH / 2];
        float2 sum = make_float2(a.x + b.x, a.y + b.y);
        float2 dif = make_float2(a.x - b.x, a.y - b.y);
        dst[2 * p]     = sum;
        dst[2 * p + 1] = cmul(dif, tw[p]);
    }
    __syncthreads();
    { float2* tmp = src; src = dst; dst = tmp; }

    // radix-4 stages: s = 2, 8, 32, 128, 512
#pragma unroll
    for (int sh = 1; sh <= 9; sh += 2) {
        const int s = 1 << sh;
        for (int idx = t; idx < NH / 4; idx += 256) {
            const int p = idx >> sh;
            const int q = idx & (s - 1);
            float2 a0 = src[idx];
            float2 a1 = src[idx + 512];
            float2 a2 = src[idx + 1024];
            float2 a3 = src[idx + 1536];
            float2 t0 = make_float2(a0.x + a2.x, a0.y + a2.y);
            float2 t1 = make_float2(a0.x - a2.x, a0.y - a2.y);
            float2 t2 = make_float2(a1.x + a3.x, a1.y + a3.y);
            float2 t3 = make_float2(a1.x - a3.x, a1.y - a3.y);
            float2 B0 = make_float2(t0.x + t2.x, t0.y + t2.y);
            float2 B2 = make_float2(t0.x - t2.x, t0.y - t2.y);
            // inverse: B1 = t1 + i*t3, B3 = t1 - i*t3
            float2 B1 = make_float2(t1.x - t3.y, t1.y + t3.x);
            float2 B3 = make_float2(t1.x + t3.y, t1.y - t3.x);
            float2 w1 = tw[idx & ~(s - 1)];    // exp(+2pi*i * p*s / NH)
            float2 w2 = make_float2(w1.x * w1.x - w1.y * w1.y, 2.f * w1.x * w1.y);
            float2 w3 = cmul(w2, w1);
            const int ob = q + (p << (sh + 2));
            dst[ob]         = B0;
            dst[ob + s]     = cmul(B1, w1);
            dst[ob + 2 * s] = cmul(B2, w2);
            dst[ob + 3 * s] = cmul(B3, w3);
        }
        __syncthreads();
        float2* tmp = src; src = dst; dst = tmp;
    }

    // unpack pairs, scale by sqrt(N)/NH = 1/32, add residual x
    const float2* xrow = (const float2*)(x + (size_t)r * NFFT);
    float2* yrow = (float2*)(y + (size_t)r * NFFT);
    for (int j = t; j < NH; j += 256) {
        float2 z  = src[j];
        float2 xp = xrow[j];
        yrow[j] = make_float2(z.x * 0.03125f + xp.x,
                              z.y * 0.03125f + xp.y);
    }
}

// ---------------------------------------------------------------------------
extern "C" void kernel_launch(void* const* d_in, const int* in_sizes, int n_in,
                              void* d_out, int out_size)
{
    const float* x    = (const float*)d_in[0];
    const float* w1re = (const float*)d_in[1];
    const float* w1im = (const float*)d_in[2];
    const float* w2re = (const float*)d_in[3];
    const float* w2im = (const float*)d_in[4];
    const float* b1re = (const float*)d_in[5];
    const float* b1im = (const float*)d_in[6];
    const float* b2re = (const float*)d_in[7];
    const float* b2im = (const float*)d_in[8];
    float* y = (float*)d_out;

    const int smem_mlp = (2 * BS * WSTR + 2 * BS * XSTR) * (int)sizeof(float); // 181248
    static int smem_set = 0;
    if (!smem_set) {
        // First call is the harness's non-captured correctness call, so the
        // attribute is set outside graph capture.
        cudaFuncSetAttribute(mlp_kernel,
                             cudaFuncAttributeMaxDynamicSharedMemorySize, smem_mlp);
        smem_set = 1;
    }

    fft_fwd_kernel<<<BATCH * CHAN, 256>>>(x);

    dim3 grid((MFREQ + MT - 1) / MT, BATCH, NB);   // 17 x 16 x 8
    mlp_kernel<<<grid, 256, smem_mlp>>>(w1re, w1im, w2re, w2im,
                                        b1re, b1im, b2re, b2im);

    fft_inv_kernel<<<BATCH * CHAN, 256>>>(x, y);
}